// round 2
// baseline (speedup 1.0000x reference)
#include <cuda_runtime.h>

#define NN 8192
#define KDIM 512
#define F 64

// Scratch (no allocations allowed in kernel_launch)
__device__ float g_z[NN * F];     // 2 MB  — z = X W^T + b
__device__ float g_zi[NN];
__device__ float g_zj[NN];
__device__ float g_S[F];          // column sums of z
__device__ float g_Wt[KDIM * F];  // W transposed to k-major [512][64]

// ---------------------------------------------------------------------------
// Prep: transpose W to k-major, zero the S accumulator (graph replays!)
// ---------------------------------------------------------------------------
__global__ void prep_kernel(const float* __restrict__ W) {
    int idx = blockIdx.x * blockDim.x + threadIdx.x;
    int stride = gridDim.x * blockDim.x;
    for (int e = idx; e < KDIM * F; e += stride) {
        int o = e % F;         // output feature (fast dim of Wt -> coalesced writes)
        int k = e / F;
        g_Wt[e] = W[o * KDIM + k];
    }
    if (idx < F) g_S[idx] = 0.0f;
}

// ---------------------------------------------------------------------------
// GEMM: z[i,o] = sum_k X[i,k] * W[o,k] + b[o]
// Block = 64 rows x 64 cols, 256 threads, 4x4 register tile per thread.
// Epilogue fuses zi = z . a1, zj = z . a2 (per row) and S += colsum(z).
// ---------------------------------------------------------------------------
__global__ void __launch_bounds__(256) gemm_kernel(
    const float* __restrict__ X, const float* __restrict__ bias,
    const float* __restrict__ a1, const float* __restrict__ a2)
{
    __shared__ float  Xs[64][68];   // padded rows: 16B-aligned, bank-clean
    __shared__ float4 Ws[64][16];   // k-major, cols packed as float4
    __shared__ float  sS[64];

    const int t  = threadIdx.x;
    const int tx = t & 15;          // col group: cols tx*4 .. tx*4+3
    const int ty = t >> 4;          // row group: rows ty*4 .. ty*4+3
    const int row0 = blockIdx.x * 64;

    if (t < 64) sS[t] = 0.0f;

    float acc[4][4] = {};
    const float4* X4  = (const float4*)X;
    const float4* Wt4 = (const float4*)g_Wt;

    for (int kc = 0; kc < KDIM; kc += 64) {
        __syncthreads();
        // Load X tile: 64 rows x 64 k (float4, coalesced)
        #pragma unroll
        for (int p = 0; p < 4; p++) {
            int idx = t + p * 256;
            int r = idx >> 4, q = idx & 15;
            float4 v = X4[(size_t)(row0 + r) * (KDIM / 4) + (kc >> 2) + q];
            *(float4*)&Xs[r][q * 4] = v;
        }
        // Load W tile: 64 k x 64 cols (already k-major, coalesced)
        #pragma unroll
        for (int p = 0; p < 4; p++) {
            int idx = t + p * 256;
            int k = idx >> 4, cg = idx & 15;
            Ws[k][cg] = Wt4[(size_t)(kc + k) * 16 + cg];
        }
        __syncthreads();

        #pragma unroll 8
        for (int k = 0; k < 64; k++) {
            float4 w = Ws[k][tx];
            float x0 = Xs[ty * 4 + 0][k];
            float x1 = Xs[ty * 4 + 1][k];
            float x2 = Xs[ty * 4 + 2][k];
            float x3 = Xs[ty * 4 + 3][k];
            acc[0][0] += x0 * w.x; acc[0][1] += x0 * w.y; acc[0][2] += x0 * w.z; acc[0][3] += x0 * w.w;
            acc[1][0] += x1 * w.x; acc[1][1] += x1 * w.y; acc[1][2] += x1 * w.z; acc[1][3] += x1 * w.w;
            acc[2][0] += x2 * w.x; acc[2][1] += x2 * w.y; acc[2][2] += x2 * w.z; acc[2][3] += x2 * w.w;
            acc[3][0] += x3 * w.x; acc[3][1] += x3 * w.y; acc[3][2] += x3 * w.z; acc[3][3] += x3 * w.w;
        }
    }

    // bias
    float4 bv = ((const float4*)bias)[tx];
    #pragma unroll
    for (int r = 0; r < 4; r++) {
        acc[r][0] += bv.x; acc[r][1] += bv.y; acc[r][2] += bv.z; acc[r][3] += bv.w;
    }

    float4 a1v = ((const float4*)a1)[tx];
    float4 a2v = ((const float4*)a2)[tx];

    #pragma unroll
    for (int r = 0; r < 4; r++) {
        int row = row0 + ty * 4 + r;
        float4 zr;
        zr.x = acc[r][0]; zr.y = acc[r][1]; zr.z = acc[r][2]; zr.w = acc[r][3];
        ((float4*)g_z)[row * 16 + tx] = zr;

        float pzi = a1v.x * zr.x + a1v.y * zr.y + a1v.z * zr.z + a1v.w * zr.w;
        float pzj = a2v.x * zr.x + a2v.y * zr.y + a2v.z * zr.z + a2v.w * zr.w;
        #pragma unroll
        for (int m = 8; m > 0; m >>= 1) {
            pzi += __shfl_xor_sync(0xffffffffu, pzi, m, 16);
            pzj += __shfl_xor_sync(0xffffffffu, pzj, m, 16);
        }
        if (tx == 0) { g_zi[row] = pzi; g_zj[row] = pzj; }
    }

    // column-sum partials -> shared -> one global atomic per column per block
    #pragma unroll
    for (int c = 0; c < 4; c++) {
        float p = acc[0][c] + acc[1][c] + acc[2][c] + acc[3][c];
        atomicAdd(&sS[tx * 4 + c], p);
    }
    __syncthreads();
    if (t < 64) atomicAdd(&g_S[t], sS[t]);
}

// ---------------------------------------------------------------------------
// Main: per row i, scan adj row (32 KB), compact neighbor indices (u16),
// gather-sum z[j] (L2-resident), apply closed-form softmax-aggregate.
// ---------------------------------------------------------------------------
__global__ void __launch_bounds__(256) attn_kernel(
    const float* __restrict__ adj, float* __restrict__ out)
{
    __shared__ unsigned short s_idx[NN];   // 16 KB — worst-case full row
    __shared__ float s_part[16 * 64];      // 4 KB  — per-group feature partials
    __shared__ int s_cnt;
    __shared__ int s_diag;

    const int i = blockIdx.x;
    const int t = threadIdx.x;
    if (t == 0) { s_cnt = 0; s_diag = 0; }
    __syncthreads();

    // --- scan adj row, compact nonzero columns ---
    const float4* arow = (const float4*)(adj + (size_t)i * NN);
    #pragma unroll
    for (int p = 0; p < 8; p++) {
        int c = t + p * 256;
        float4 v = arow[c];
        int j = c * 4;
        if (v.x != 0.0f) { if (j     == i) s_diag = 1; else s_idx[atomicAdd(&s_cnt, 1)] = (unsigned short)(j    ); }
        if (v.y != 0.0f) { if (j + 1 == i) s_diag = 1; else s_idx[atomicAdd(&s_cnt, 1)] = (unsigned short)(j + 1); }
        if (v.z != 0.0f) { if (j + 2 == i) s_diag = 1; else s_idx[atomicAdd(&s_cnt, 1)] = (unsigned short)(j + 2); }
        if (v.w != 0.0f) { if (j + 3 == i) s_diag = 1; else s_idx[atomicAdd(&s_cnt, 1)] = (unsigned short)(j + 3); }
    }
    __syncthreads();
    const int cnt  = s_cnt;
    const int diag = s_diag;

    // --- gather T = sum_{neighbors} z[j] : 16 groups x 16 float4-chunks ---
    const int chunk = t & 15;   // which float4 of the 64-float z row
    const int group = t >> 4;
    float4 acc = make_float4(0.f, 0.f, 0.f, 0.f);
    const float4* z4 = (const float4*)g_z;
    for (int n = group; n < cnt; n += 16) {
        float4 v = z4[(int)s_idx[n] * 16 + chunk];
        acc.x += v.x; acc.y += v.y; acc.z += v.z; acc.w += v.w;
    }
    ((float4*)s_part)[group * 16 + chunk] = acc;
    __syncthreads();

    // --- closed-form output row ---
    if (t < 64) {
        float T = 0.0f;
        #pragma unroll
        for (int g = 0; g < 16; g++) T += s_part[g * 64 + t];

        float zif = g_z[i * 64 + t];
        float zi  = g_zi[i];
        float zj  = g_zj[i];

        float v1 = zi > 0.0f ? zi : 0.01f * zi;          // leaky_relu
        float e1 = expf(v1);
        float e2 = 0.0f;
        if (diag) {
            float v2 = zi + zj;
            v2 = v2 > 0.0f ? v2 : 0.01f * v2;
            e2 = expf(v2);
        }
        float D   = (float)(NN - cnt - diag) + (float)cnt * e1 + (diag ? e2 : 0.0f);
        float num = g_S[t] + (e1 - 1.0f) * T + (diag ? (e2 - 1.0f) * zif : 0.0f);
        float h   = zif - num / D;
        out[i * 64 + t] = h > 0.0f ? h : 0.0f;
    }
}

// ---------------------------------------------------------------------------
extern "C" void kernel_launch(void* const* d_in, const int* in_sizes, int n_in,
                              void* d_out, int out_size) {
    const float* X   = (const float*)d_in[0];  // (8192, 512)
    const float* adj = (const float*)d_in[1];  // (8192, 8192)
    // d_in[2] = eye_matrix — deliberately unused (identity is known analytically)
    const float* W   = (const float*)d_in[3];  // (64, 512)
    const float* b   = (const float*)d_in[4];  // (64,)
    const float* a1  = (const float*)d_in[5];  // (1, 64)
    const float* a2  = (const float*)d_in[6];  // (1, 64)
    float* out = (float*)d_out;                // (8192, 64)

    prep_kernel<<<64, 256>>>(W);
    gemm_kernel<<<NN / 64, 256>>>(X, b, a1, a2);
    attn_kernel<<<NN, 256>>>(adj, out);
}